// round 16
// baseline (speedup 1.0000x reference)
#include <cuda_runtime.h>
#include <math.h>
#include <stdint.h>

#define DD 512
#define KCLS 4
#define MP 8
#define JJ 32
#define INV_EPS 20.0f
#define GAMMA_M 0.999f
#define NMAX 200704
#define TOK 128

typedef unsigned long long ull;

// ---------------- device scratch (no allocations) ---------------------------
__device__ __align__(16) float gPN[JJ * DD];
__device__ __align__(16) float gS1[JJ];
__device__ __align__(16) float gS2[JJ];
__device__ __align__(16) float gCst[4];               // Q0, R0, B2
__device__ __align__(16) float gGG[DD];               // g^2
__device__ __align__(16) float gGB[DD];               // g*b
// W image for LDG GEMM: float2[kq][c][jg][parity]  (kq<128, c<4, jg<8, par<2)
// col = jg*4 + c ; entry (kq,c,jg) = 16B = kpairs 2kq, 2kq+1 of col
__device__ __align__(16) float2 gW2[128 * 64];
__device__ __align__(16) float4 gABC[NMAX];
__device__ __align__(16) float gE[NMAX * MP];
__device__ unsigned char gPred[NMAX];
__device__ unsigned char gBucket[NMAX];
__device__ __align__(16) float gC[3][JJ];
__device__ __align__(16) float gBcnt[KCLS];
__device__ __align__(16) float gF[JJ * DD];
__device__ __align__(16) float gNcnt[JJ];

// ---------------- helpers ----------------------------------------------------
__device__ __forceinline__ void fma2(ull& acc, ull a, ull b) {
    asm("fma.rn.f32x2 %0, %1, %2, %0;" : "+l"(acc) : "l"(a), "l"(b));
}
__device__ __forceinline__ float fold2(ull v) {
    float lo, hi;
    asm("mov.b64 {%0, %1}, %2;" : "=f"(lo), "=f"(hi) : "l"(v));
    return lo + hi;
}

__global__ void nopKernel(int) {}

// ---------------- kernel 1: init ---------------------------------------------
__global__ void initKernel(const float* __restrict__ protos,
                           const float* __restrict__ g,
                           const float* __restrict__ b) {
    int tid = threadIdx.x;
    int w = tid >> 5, l = tid & 31;     // warp w handles prototype j = w

    for (int i = tid; i < JJ * DD; i += 1024) gF[i] = 0.f;
    if (tid < 3 * JJ) ((float*)gC)[tid] = 0.f;
    if (tid < JJ) gNcnt[tid] = 0.f;
    if (tid < KCLS) gBcnt[tid] = 0.f;
    if (tid < DD) { float gv = g[tid]; gGG[tid] = gv * gv; gGB[tid] = gv * b[tid]; }

    {
        const float* p = protos + (size_t)w * DD;
        float v[16];
        float ss = 0.f;
#pragma unroll
        for (int i = 0; i < 8; i++) {
            int pr = l + 32 * i;
            v[2 * i]     = p[2 * pr];
            v[2 * i + 1] = p[2 * pr + 1];
            ss += v[2 * i] * v[2 * i] + v[2 * i + 1] * v[2 * i + 1];
        }
#pragma unroll
        for (int o = 16; o > 0; o >>= 1) ss += __shfl_xor_sync(0xffffffffu, ss, o);
        float inv = 1.f / fmaxf(sqrtf(ss), 1e-12f);
        float s1 = 0.f, s2 = 0.f;
        int jgw = w >> 2, cw = w & 3;    // col w = jgw*4 + cw
#pragma unroll
        for (int i = 0; i < 8; i++) {
            int pr = l + 32 * i;          // global k-pair index 0..255
            int d0 = 2 * pr, d1 = d0 + 1;
            float pn0 = v[2 * i] * inv, pn1 = v[2 * i + 1] * inv;
            gPN[w * DD + d0] = pn0;
            gPN[w * DD + d1] = pn1;
            float g0 = g[d0], g1 = g[d1];
            s1 += g0 * pn0 + g1 * pn1;
            s2 += b[d0] * pn0 + b[d1] * pn1;
            int kq = pr >> 1, par = pr & 1;
            gW2[kq * 64 + cw * 16 + jgw * 2 + par] = make_float2(g0 * pn0, g1 * pn1);
        }
#pragma unroll
        for (int o = 16; o > 0; o >>= 1) {
            s1 += __shfl_xor_sync(0xffffffffu, s1, o);
            s2 += __shfl_xor_sync(0xffffffffu, s2, o);
        }
        if (l == 0) { gS1[w] = s1; gS2[w] = s2; }
    }

    if (w == 0) {
        float q0 = 0.f, r0 = 0.f, b2 = 0.f;
#pragma unroll
        for (int i = 0; i < 16; i++) {
            int d = l + 32 * i;
            float gv = g[d], bv = b[d];
            q0 += gv * gv; r0 += gv * bv; b2 += bv * bv;
        }
#pragma unroll
        for (int o = 16; o > 0; o >>= 1) {
            q0 += __shfl_xor_sync(0xffffffffu, q0, o);
            r0 += __shfl_xor_sync(0xffffffffu, r0, o);
            b2 += __shfl_xor_sync(0xffffffffu, b2, o);
        }
        if (l == 0) { gCst[0] = q0; gCst[1] = r0; gCst[2] = b2; gCst[3] = 0.f; }
    }
}

// ---------------- kernel 2: fused stats + LDG/L1 FFMA2 GEMM + epilogue --------
__global__ void __launch_bounds__(256, 3)
fusedKernel(const float* __restrict__ X,
            const int* __restrict__ gt,
            const float* __restrict__ mg,
            const float* __restrict__ mb,
            float* __restrict__ outseg,
            int n) {
    __shared__ float Msm[TOK * 36];       // 18432 B mask tile
    __shared__ float sSH[TOK * 5];        // stats partials (upper half)
    __shared__ float sS1[JJ], sS2[JJ];
    __shared__ float sCp[4][JJ];
    __shared__ float sBp[KCLS];

    int tid = threadIdx.x;
    int tokBase = blockIdx.x * TOK;
    int tg = tid >> 3;                    // rows tg + 32*i  (i = 0..3)
    int jg = tid & 7;                     // cols jg*4 .. jg*4+3

    if (tid < JJ) { sS1[tid] = gS1[tid]; sS2[tid] = gS2[tid]; }
    if (tid < 4 * JJ) ((float*)sCp)[tid] = 0.f;
    if (tid < KCLS) sBp[tid] = 0.f;

    // ---- stats pass: thread covers row (tid&127), k-half (tid>>7) ----
    float sx = 0.f, sxx = 0.f, q2 = 0.f, q1 = 0.f, r1 = 0.f;
    {
        int rowOwn = tid & 127;
        int half = tid >> 7;
        int tokS = tokBase + rowOwn;
        const float4* xs = (const float4*)(X + (size_t)(tokS < n ? tokS : 0) * DD) + half * 64;
        const float4* ggp = (const float4*)gGG + half * 64;
        const float4* gbp = (const float4*)gGB + half * 64;
#pragma unroll 4
        for (int i = 0; i < 64; i++) {
            float4 v = xs[i];
            float4 g4 = ggp[i];
            float4 b4 = gbp[i];
            float t;
            t = v.x * v.x; sx += v.x; sxx += t; q2 = fmaf(t, g4.x, q2); q1 = fmaf(v.x, g4.x, q1); r1 = fmaf(v.x, b4.x, r1);
            t = v.y * v.y; sx += v.y; sxx += t; q2 = fmaf(t, g4.y, q2); q1 = fmaf(v.y, g4.y, q1); r1 = fmaf(v.y, b4.y, r1);
            t = v.z * v.z; sx += v.z; sxx += t; q2 = fmaf(t, g4.z, q2); q1 = fmaf(v.z, g4.z, q1); r1 = fmaf(v.z, b4.z, r1);
            t = v.w * v.w; sx += v.w; sxx += t; q2 = fmaf(t, g4.w, q2); q1 = fmaf(v.w, g4.w, q1); r1 = fmaf(v.w, b4.w, r1);
        }
        if (half == 1) {
            float* s = sSH + rowOwn * 5;
            s[0] = sx; s[1] = sxx; s[2] = q2; s[3] = q1; s[4] = r1;
        }
    }

    // ---- GEMM: all operands via LDG/L1 (dedup'd), zero smem traffic ----
    ull acc[4][4];
#pragma unroll
    for (int i = 0; i < 4; i++)
#pragma unroll
        for (int c = 0; c < 4; c++) acc[i][c] = 0ull;

    const float* xr0 = X + (size_t)((tokBase + tg      < n) ? tokBase + tg      : 0) * DD;
    const float* xr1 = X + (size_t)((tokBase + tg + 32 < n) ? tokBase + tg + 32 : 0) * DD;
    const float* xr2 = X + (size_t)((tokBase + tg + 64 < n) ? tokBase + tg + 64 : 0) * DD;
    const float* xr3 = X + (size_t)((tokBase + tg + 96 < n) ? tokBase + tg + 96 : 0) * DD;
    const float2* wbase = gW2 + jg * 2;

#pragma unroll 4
    for (int kq = 0; kq < 128; kq++) {
        ulonglong2 wv0 = *(const ulonglong2*)(wbase + kq * 64);
        ulonglong2 wv1 = *(const ulonglong2*)(wbase + kq * 64 + 16);
        ulonglong2 wv2 = *(const ulonglong2*)(wbase + kq * 64 + 32);
        ulonglong2 wv3 = *(const ulonglong2*)(wbase + kq * 64 + 48);
        ulonglong2 x0 = *(const ulonglong2*)(xr0 + kq * 4);
        ulonglong2 x1 = *(const ulonglong2*)(xr1 + kq * 4);
        ulonglong2 x2 = *(const ulonglong2*)(xr2 + kq * 4);
        ulonglong2 x3 = *(const ulonglong2*)(xr3 + kq * 4);
        fma2(acc[0][0], x0.x, wv0.x); fma2(acc[0][0], x0.y, wv0.y);
        fma2(acc[0][1], x0.x, wv1.x); fma2(acc[0][1], x0.y, wv1.y);
        fma2(acc[0][2], x0.x, wv2.x); fma2(acc[0][2], x0.y, wv2.y);
        fma2(acc[0][3], x0.x, wv3.x); fma2(acc[0][3], x0.y, wv3.y);
        fma2(acc[1][0], x1.x, wv0.x); fma2(acc[1][0], x1.y, wv0.y);
        fma2(acc[1][1], x1.x, wv1.x); fma2(acc[1][1], x1.y, wv1.y);
        fma2(acc[1][2], x1.x, wv2.x); fma2(acc[1][2], x1.y, wv2.y);
        fma2(acc[1][3], x1.x, wv3.x); fma2(acc[1][3], x1.y, wv3.y);
        fma2(acc[2][0], x2.x, wv0.x); fma2(acc[2][0], x2.y, wv0.y);
        fma2(acc[2][1], x2.x, wv1.x); fma2(acc[2][1], x2.y, wv1.y);
        fma2(acc[2][2], x2.x, wv2.x); fma2(acc[2][2], x2.y, wv2.y);
        fma2(acc[2][3], x2.x, wv3.x); fma2(acc[2][3], x2.y, wv3.y);
        fma2(acc[3][0], x3.x, wv0.x); fma2(acc[3][0], x3.y, wv0.y);
        fma2(acc[3][1], x3.x, wv1.x); fma2(acc[3][1], x3.y, wv1.y);
        fma2(acc[3][2], x3.x, wv2.x); fma2(acc[3][2], x3.y, wv2.y);
        fma2(acc[3][3], x3.x, wv3.x); fma2(acc[3][3], x3.y, wv3.y);
    }

    // dump masks to smem: row tg+32i, col jg*4+c
#pragma unroll
    for (int i = 0; i < 4; i++)
#pragma unroll
        for (int c = 0; c < 4; c++)
            Msm[(tg + 32 * i) * 36 + jg * 4 + c] = fold2(acc[i][c]);
    __syncthreads();

    // epilogue: threads 0..127, one per token
    if (tid < TOK) {
        int tok = tokBase + tid;
        const float* s = sSH + tid * 5;
        sx += s[0]; sxx += s[1]; q2 += s[2]; q1 += s[3]; r1 += s[4];

        float Q0 = gCst[0], R0 = gCst[1], B2 = gCst[2];
        const float invD = 1.f / 512.f;
        float mu = sx * invD;
        float var = sxx * invD - mu * mu;
        float istd = rsqrtf(var + 1e-5f);
        float ysq = istd * istd * (q2 - 2.f * mu * q1 + mu * mu * Q0)
                  + 2.f * istd * (r1 - mu * R0) + B2;
        float inv = 1.f / fmaxf(sqrtf(fmaxf(ysq, 0.f)), 1e-12f);
        float4 abc = make_float4(istd * inv, -istd * mu * inv, inv, 0.f);

        if (tok < n) {
            gABC[tok] = abc;
            float m[32];
            float mx[4];
#pragma unroll
            for (int k = 0; k < 4; k++) {
                float best = -1e30f;
#pragma unroll
                for (int mm = 0; mm < 8; mm++) {
                    int j = k * 8 + mm;
                    float v = abc.x * Msm[tid * 36 + j] + abc.y * sS1[j] + abc.z * sS2[j];
                    m[j] = v;
                    best = fmaxf(best, v);
                }
                mx[k] = best;
            }
            float mu4 = 0.25f * (mx[0] + mx[1] + mx[2] + mx[3]);
            float var4 = 0.f;
#pragma unroll
            for (int k = 0; k < 4; k++) { float d = mx[k] - mu4; var4 += d * d; }
            var4 *= 0.25f;
            float is4 = 1.f / sqrtf(var4 + 1e-5f);
            float o[4];
            int pred = 0; float bo = -1e30f;
#pragma unroll
            for (int k = 0; k < 4; k++) {
                o[k] = (mx[k] - mu4) * is4 * mg[k] + mb[k];
                if (o[k] > bo) { bo = o[k]; pred = k; }
            }
            *(float4*)(outseg + (size_t)tok * 4) = make_float4(o[0], o[1], o[2], o[3]);
            gPred[tok] = (unsigned char)pred;

            int kk = gt[tok];
            float e[8];
#pragma unroll
            for (int mm = 0; mm < 8; mm++) e[mm] = expf(m[kk * 8 + mm] * INV_EPS);
            *(float4*)(gE + (size_t)tok * 8)     = make_float4(e[0], e[1], e[2], e[3]);
            *(float4*)(gE + (size_t)tok * 8 + 4) = make_float4(e[4], e[5], e[6], e[7]);
#pragma unroll
            for (int mm = 0; mm < 8; mm++)
                atomicAdd(&sCp[tid >> 5][kk * 8 + mm], e[mm]);
            atomicAdd(&sBp[kk], 1.f);
        }
    }
    __syncthreads();
    if (tid < JJ) {
        float s = sCp[0][tid] + sCp[1][tid] + sCp[2][tid] + sCp[3][tid];
        if (s != 0.f) atomicAdd(&gC[0][tid], s);
    }
    if (tid < KCLS && sBp[tid] != 0.f) atomicAdd(&gBcnt[tid], sBp[tid]);
}

// ---------------- kernel 3: one sinkhorn column iteration --------------------
__global__ void __launch_bounds__(256) sinkIterKernel(const int* __restrict__ gt,
                                                      int n, int src, int dst) {
    __shared__ float alpha[JJ];
    __shared__ float Cp[8][JJ];
    __shared__ float Bk[KCLS];
    int tid = threadIdx.x;
    int wrp = tid >> 5;
    if (tid < JJ) alpha[tid] = 1.f / fmaxf(8.f * gC[src][tid], 1e-30f);
    if (tid < 8 * JJ) ((float*)Cp)[tid] = 0.f;
    if (tid < KCLS) Bk[tid] = fmaxf(gBcnt[tid], 1.f);
    __syncthreads();

    int stride = gridDim.x * blockDim.x;
    for (int tok = blockIdx.x * blockDim.x + tid; tok < n; tok += stride) {
        int k = gt[tok];
        float4 a = *(const float4*)(gE + (size_t)tok * 8);
        float4 b4 = *(const float4*)(gE + (size_t)tok * 8 + 4);
        float e[8] = {a.x, a.y, a.z, a.w, b4.x, b4.y, b4.z, b4.w};
        float denom = 0.f;
#pragma unroll
        for (int mm = 0; mm < 8; mm++) denom += e[mm] * alpha[k * 8 + mm];
        float beta = 1.f / fmaxf(Bk[k] * denom, 1e-30f);
#pragma unroll
        for (int mm = 0; mm < 8; mm++) atomicAdd(&Cp[wrp][k * 8 + mm], e[mm] * beta);
    }
    __syncthreads();
    if (tid < JJ) {
        float s = 0.f;
#pragma unroll
        for (int w = 0; w < 8; w++) s += Cp[w][tid];
        if (s != 0.f) atomicAdd(&gC[dst][tid], s);
    }
}

// ---------------- kernel 4: bucket assignment --------------------------------
__global__ void __launch_bounds__(256) bucketKernel(const int* __restrict__ gt, int n) {
    __shared__ float invc[JJ];
    int tid = threadIdx.x;
    if (tid < JJ) invc[tid] = 1.f / fmaxf(gC[2][tid], 1e-30f);
    __syncthreads();
    int stride = gridDim.x * blockDim.x;
    for (int tok = blockIdx.x * blockDim.x + tid; tok < n; tok += stride) {
        int k = gt[tok];
        unsigned char bkt = 255;
        if (gPred[tok] == (unsigned char)k) {
            float4 a = *(const float4*)(gE + (size_t)tok * 8);
            float4 b4 = *(const float4*)(gE + (size_t)tok * 8 + 4);
            float e[8] = {a.x, a.y, a.z, a.w, b4.x, b4.y, b4.z, b4.w};
            float best = -1e30f; int bi = 0;
#pragma unroll
            for (int mm = 0; mm < 8; mm++) {
                float v = e[mm] * invc[k * 8 + mm];
                if (v > best) { best = v; bi = mm; }
            }
            bkt = (unsigned char)(k * 8 + bi);
        }
        gBucket[tok] = bkt;
    }
}

// ---------------- kernel 5: aggregation (register accumulators) --------------
#define AGG_SLICES 44
__global__ void __launch_bounds__(256) aggKernel(const float* __restrict__ X,
                                                 const float* __restrict__ g,
                                                 const float* __restrict__ b,
                                                 int n) {
    int l = threadIdx.x & 31;
    int wgid = blockIdx.x * 8 + (threadIdx.x >> 5);
    int bucket = wgid & 31;
    int slice = wgid >> 5;
    if (slice >= AGG_SLICES) return;

    int chunk = (n + AGG_SLICES - 1) / AGG_SLICES;
    int start = slice * chunk;
    int end = min(start + chunk, n);

    float gl[16], bl[16], acc[16];
#pragma unroll
    for (int i = 0; i < 16; i++) {
        gl[i] = g[l + 32 * i];
        bl[i] = b[l + 32 * i];
        acc[i] = 0.f;
    }
    int cnt = 0;

    for (int t0 = start; t0 < end; t0 += 32) {
        int tok = t0 + l;
        int myb = (tok < end) ? (int)gBucket[tok] : -1;
        unsigned mask = __ballot_sync(0xffffffffu, myb == bucket);
        cnt += __popc(mask);
        while (mask) {
            int bit = __ffs(mask) - 1;
            mask &= mask - 1;
            int th = t0 + bit;
            float4 abc = gABC[th];
            const float* x = X + (size_t)th * DD;
#pragma unroll
            for (int i = 0; i < 16; i++) {
                acc[i] += fmaf(abc.x * gl[i], x[l + 32 * i],
                               fmaf(abc.y, gl[i], abc.z * bl[i]));
            }
        }
    }
#pragma unroll
    for (int i = 0; i < 16; i++)
        if (acc[i] != 0.f) atomicAdd(&gF[bucket * DD + l + 32 * i], acc[i]);
    if (l == 0 && cnt > 0) atomicAdd(&gNcnt[bucket], (float)cnt);
}

// ---------------- kernel 6: finalize new prototypes ---------------------------
__global__ void finalKernel(float* __restrict__ outp) {
    int tid = threadIdx.x;
    int w = tid >> 5, l = tid & 31;
    int k = w >> 3;

    float nj = gNcnt[w];
    float nsum = 0.f;
#pragma unroll
    for (int mm = 0; mm < 8; mm++) nsum += gNcnt[k * 8 + mm];
    bool valid = (nj != 0.f) && (gBcnt[k] > 0.f) && (nsum > 0.f);

    float v[16];
    float ss = 0.f;
#pragma unroll
    for (int i = 0; i < 16; i++) {
        v[i] = gF[w * DD + l + 32 * i];
        ss += v[i] * v[i];
    }
#pragma unroll
    for (int o = 16; o > 0; o >>= 1) ss += __shfl_xor_sync(0xffffffffu, ss, o);
    float inv = 1.f / fmaxf(sqrtf(ss), 1e-12f);

    float out[16];
    float ss2 = 0.f;
#pragma unroll
    for (int i = 0; i < 16; i++) {
        float fn = v[i] * inv;
        float base = gPN[w * DD + l + 32 * i];
        float r = valid ? (GAMMA_M * base + (1.f - GAMMA_M) * fn) : base;
        out[i] = r;
        ss2 += r * r;
    }
#pragma unroll
    for (int o = 16; o > 0; o >>= 1) ss2 += __shfl_xor_sync(0xffffffffu, ss2, o);
    float inv2 = 1.f / fmaxf(sqrtf(ss2), 1e-12f);
#pragma unroll
    for (int i = 0; i < 16; i++)
        outp[w * DD + l + 32 * i] = out[i] * inv2;
}

// ---------------- launch ------------------------------------------------------
extern "C" void kernel_launch(void* const* d_in, const int* in_sizes, int n_in,
                              void* d_out, int out_size) {
    const float* feats  = (const float*)d_in[0];
    const float* ln_g   = (const float*)d_in[1];
    const float* ln_b   = (const float*)d_in[2];
    const float* mg     = (const float*)d_in[3];
    const float* mb     = (const float*)d_in[4];
    const float* protos = (const float*)d_in[5];
    const int*   gt     = (const int*)d_in[6];

    int n = in_sizes[0] / DD;
    float* outseg = (float*)d_out;
    float* outp   = (float*)d_out + (size_t)(out_size - JJ * DD);

    initKernel<<<1, 1024>>>(protos, ln_g, ln_b);
    nopKernel<<<1, 32>>>(0);
    nopKernel<<<1, 32>>>(1);
    fusedKernel<<<(n + TOK - 1) / TOK, 256>>>(feats, gt, mg, mb, outseg, n);
    sinkIterKernel<<<512, 256>>>(gt, n, 0, 1);
    sinkIterKernel<<<512, 256>>>(gt, n, 1, 2);
    bucketKernel<<<512, 256>>>(gt, n);
    aggKernel<<<(32 * AGG_SLICES + 7) / 8, 256>>>(feats, ln_g, ln_b, n);
    finalKernel<<<1, 1024>>>(outp);
}

// round 17
// speedup vs baseline: 1.9718x; 1.9718x over previous
#include <cuda_runtime.h>
#include <cuda_bf16.h>
#include <math.h>
#include <stdint.h>

#define DD 512
#define KCLS 4
#define MP 8
#define JJ 32
#define INV_EPS 20.0f
#define GAMMA_M 0.999f
#define NMAX 200704
#define BROW 260            // u32 row stride for W images (pad: 260 % 32 = 4 -> conflict-free)

// ---------------- device scratch (no allocations) ---------------------------
__device__ __align__(16) float gPN[JJ * DD];
__device__ __align__(16) float gS1[JJ];
__device__ __align__(16) float gS2[JJ];
__device__ __align__(16) float gCst[4];                 // Q0, R0, B2
__device__ __align__(16) float4 gGGB[DD / 2];           // (gg0,gg1,gb0,gb1) per k-pair
__device__ __align__(16) uint32_t gW2[2 * JJ * BROW];   // bf16x2 W images: hi then lo
__device__ __align__(16) float4 gABC[NMAX];
__device__ __align__(16) float gE[NMAX * MP];
__device__ unsigned char gPred[NMAX];
__device__ unsigned char gBucket[NMAX];
__device__ __align__(16) float gC[3][JJ];
__device__ __align__(16) float gBcnt[KCLS];
__device__ __align__(16) float gF[JJ * DD];
__device__ __align__(16) float gNcnt[JJ];

// ---------------- helpers ----------------------------------------------------
__device__ __forceinline__ uint32_t packbf(float lo, float hi) {
    uint32_t r;
    asm("cvt.rn.bf16x2.f32 %0, %1, %2;" : "=r"(r) : "f"(hi), "f"(lo));
    return r;
}
__device__ __forceinline__ float2 residbf(float2 v, uint32_t h) {
    __nv_bfloat162 hb = *reinterpret_cast<__nv_bfloat162*>(&h);
    return make_float2(v.x - __bfloat162float(hb.x), v.y - __bfloat162float(hb.y));
}
__device__ __forceinline__ void mma_bf16(float* c, uint32_t a0, uint32_t a1,
                                         uint32_t a2, uint32_t a3,
                                         uint32_t b0, uint32_t b1) {
    asm volatile(
        "mma.sync.aligned.m16n8k16.row.col.f32.bf16.bf16.f32 "
        "{%0,%1,%2,%3}, {%4,%5,%6,%7}, {%8,%9}, {%0,%1,%2,%3};"
        : "+f"(c[0]), "+f"(c[1]), "+f"(c[2]), "+f"(c[3])
        : "r"(a0), "r"(a1), "r"(a2), "r"(a3), "r"(b0), "r"(b1));
}
__device__ __forceinline__ void stat2(float2 v, float gg0, float gg1,
                                      float gb0, float gb1,
                                      float& sx, float& sxx, float& q2,
                                      float& q1, float& r1) {
    float x2;
    x2 = v.x * v.x; sx += v.x; sxx += x2;
    q2 = fmaf(x2, gg0, q2); q1 = fmaf(v.x, gg0, q1); r1 = fmaf(v.x, gb0, r1);
    x2 = v.y * v.y; sx += v.y; sxx += x2;
    q2 = fmaf(x2, gg1, q2); q1 = fmaf(v.y, gg1, q1); r1 = fmaf(v.y, gb1, r1);
}

__global__ void nopKernel(int) {}

// ---------------- kernel 1: init ---------------------------------------------
__global__ void initKernel(const float* __restrict__ protos,
                           const float* __restrict__ g,
                           const float* __restrict__ b) {
    int tid = threadIdx.x;
    int w = tid >> 5, l = tid & 31;     // warp w handles prototype j = w

    for (int i = tid; i < JJ * DD; i += 1024) gF[i] = 0.f;
    if (tid < 3 * JJ) ((float*)gC)[tid] = 0.f;
    if (tid < JJ) gNcnt[tid] = 0.f;
    if (tid < KCLS) gBcnt[tid] = 0.f;
    if (tid < DD / 2) {
        int d = tid * 2;
        float g0 = g[d], g1 = g[d + 1];
        gGGB[tid] = make_float4(g0 * g0, g1 * g1, g0 * b[d], g1 * b[d + 1]);
    }

    {   // prototype j = w: normalize, build W bf16 hi/lo pair images
        const float* p = protos + (size_t)w * DD;
        float v[16];
        float ss = 0.f;
#pragma unroll
        for (int i = 0; i < 8; i++) {
            int pr = l + 32 * i;             // pair index
            v[2 * i]     = p[2 * pr];
            v[2 * i + 1] = p[2 * pr + 1];
            ss += v[2 * i] * v[2 * i] + v[2 * i + 1] * v[2 * i + 1];
        }
#pragma unroll
        for (int o = 16; o > 0; o >>= 1) ss += __shfl_xor_sync(0xffffffffu, ss, o);
        float inv = 1.f / fmaxf(sqrtf(ss), 1e-12f);
        float s1 = 0.f, s2 = 0.f;
#pragma unroll
        for (int i = 0; i < 8; i++) {
            int pr = l + 32 * i;
            int d0 = 2 * pr, d1 = d0 + 1;
            float pn0 = v[2 * i] * inv, pn1 = v[2 * i + 1] * inv;
            gPN[w * DD + d0] = pn0;
            gPN[w * DD + d1] = pn1;
            float g0 = g[d0], g1 = g[d1];
            s1 += g0 * pn0 + g1 * pn1;
            s2 += b[d0] * pn0 + b[d1] * pn1;
            float w0 = g0 * pn0, w1 = g1 * pn1;
            uint32_t hi = packbf(w0, w1);
            float2 rs = residbf(make_float2(w0, w1), hi);
            uint32_t lo = packbf(rs.x, rs.y);
            gW2[w * BROW + pr] = hi;
            gW2[JJ * BROW + w * BROW + pr] = lo;
        }
#pragma unroll
        for (int o = 16; o > 0; o >>= 1) {
            s1 += __shfl_xor_sync(0xffffffffu, s1, o);
            s2 += __shfl_xor_sync(0xffffffffu, s2, o);
        }
        if (l == 0) { gS1[w] = s1; gS2[w] = s2; }
    }

    if (w == 0) {
        float q0 = 0.f, r0 = 0.f, b2 = 0.f;
#pragma unroll
        for (int i = 0; i < 16; i++) {
            int d = l + 32 * i;
            float gv = g[d], bv = b[d];
            q0 += gv * gv; r0 += gv * bv; b2 += bv * bv;
        }
#pragma unroll
        for (int o = 16; o > 0; o >>= 1) {
            q0 += __shfl_xor_sync(0xffffffffu, q0, o);
            r0 += __shfl_xor_sync(0xffffffffu, r0, o);
            b2 += __shfl_xor_sync(0xffffffffu, b2, o);
        }
        if (l == 0) { gCst[0] = q0; gCst[1] = r0; gCst[2] = b2; gCst[3] = 0.f; }
    }
}

// ---------------- kernel 2: fused stats + bf16-split mma GEMM + epilogue ------
// dynamic smem: W hi/lo images 2*32*260*4 = 66560 B; overlaid later by masks[128][36]
#define DSM_BYTES (2 * JJ * BROW * 4)

__global__ void __launch_bounds__(256) fusedKernel(const float* __restrict__ X,
                                                   const int* __restrict__ gt,
                                                   const float* __restrict__ mg,
                                                   const float* __restrict__ mb,
                                                   float* __restrict__ outseg,
                                                   int n) {
    extern __shared__ char dsm[];
    uint32_t* BsmHi = (uint32_t*)dsm;
    uint32_t* BsmLo = BsmHi + JJ * BROW;
    float* Msm = (float*)dsm;                 // overlay after mma loop
    __shared__ float4 sGGB[DD / 2];
    __shared__ float4 sABS[128];
    __shared__ float sS1[JJ], sS2[JJ];
    __shared__ float sCp[4][JJ];
    __shared__ float sBp[KCLS];

    int tid = threadIdx.x;
    int w = tid >> 5, lane = tid & 31;
    int q = lane & 3, rq = lane >> 2;
    int tokBase = blockIdx.x * 128;

    {   // stage W images (4160 uint4)
        const uint4* src = (const uint4*)gW2;
        uint4* dst = (uint4*)dsm;
        for (int i = tid; i < (2 * JJ * BROW) / 4; i += 256) dst[i] = src[i];
    }
    for (int i = tid; i < DD / 2; i += 256) sGGB[i] = gGGB[i];
    if (tid < JJ) { sS1[tid] = gS1[tid]; sS2[tid] = gS2[tid]; }
    if (tid < 4 * JJ) ((float*)sCp)[tid] = 0.f;
    if (tid < KCLS) sBp[tid] = 0.f;
    __syncthreads();

    int r0 = tokBase + w * 16 + rq;       // this thread's two A rows
    int r1 = r0 + 8;
    const float* x0 = X + (size_t)(r0 < n ? r0 : 0) * DD;
    const float* x1 = X + (size_t)(r1 < n ? r1 : 0) * DD;

    float acc[4][4] = {};
    float sxA = 0.f, sxxA = 0.f, q2A = 0.f, q1A = 0.f, r1A = 0.f;
    float sxB = 0.f, sxxB = 0.f, q2B = 0.f, q1B = 0.f, r1B = 0.f;

    const uint32_t* bRowHi = BsmHi + rq * BROW;
    const uint32_t* bRowLo = BsmLo + rq * BROW;

#pragma unroll 4
    for (int kb = 0; kb < DD; kb += 16) {
        int kp = (kb >> 1) + q;
        float2 xa0 = *(const float2*)(x0 + kb + 2 * q);
        float2 xa2 = *(const float2*)(x0 + kb + 2 * q + 8);
        float2 xb0 = *(const float2*)(x1 + kb + 2 * q);
        float2 xb2 = *(const float2*)(x1 + kb + 2 * q + 8);
        float4 gq0 = sGGB[kp];
        float4 gq2 = sGGB[kp + 4];

        stat2(xa0, gq0.x, gq0.y, gq0.z, gq0.w, sxA, sxxA, q2A, q1A, r1A);
        stat2(xa2, gq2.x, gq2.y, gq2.z, gq2.w, sxA, sxxA, q2A, q1A, r1A);
        stat2(xb0, gq0.x, gq0.y, gq0.z, gq0.w, sxB, sxxB, q2B, q1B, r1B);
        stat2(xb2, gq2.x, gq2.y, gq2.z, gq2.w, sxB, sxxB, q2B, q1B, r1B);

        uint32_t a0h = packbf(xa0.x, xa0.y);
        uint32_t a1h = packbf(xb0.x, xb0.y);
        uint32_t a2h = packbf(xa2.x, xa2.y);
        uint32_t a3h = packbf(xb2.x, xb2.y);
        float2 rr;
        rr = residbf(xa0, a0h); uint32_t a0l = packbf(rr.x, rr.y);
        rr = residbf(xb0, a1h); uint32_t a1l = packbf(rr.x, rr.y);
        rr = residbf(xa2, a2h); uint32_t a2l = packbf(rr.x, rr.y);
        rr = residbf(xb2, a3h); uint32_t a3l = packbf(rr.x, rr.y);

#pragma unroll
        for (int nt = 0; nt < 4; nt++) {
            uint32_t bh0 = bRowHi[nt * 8 * BROW + kp];
            uint32_t bh1 = bRowHi[nt * 8 * BROW + kp + 4];
            uint32_t bl0 = bRowLo[nt * 8 * BROW + kp];
            uint32_t bl1 = bRowLo[nt * 8 * BROW + kp + 4];
            mma_bf16(acc[nt], a0h, a1h, a2h, a3h, bh0, bh1);
            mma_bf16(acc[nt], a0h, a1h, a2h, a3h, bl0, bl1);
            mma_bf16(acc[nt], a0l, a1l, a2l, a3l, bh0, bh1);
        }
    }

    // quad-reduce stats (lanes differing in bits 0,1 share the same rows)
#pragma unroll
    for (int o = 1; o <= 2; o <<= 1) {
        sxA  += __shfl_xor_sync(0xffffffffu, sxA,  o);
        sxxA += __shfl_xor_sync(0xffffffffu, sxxA, o);
        q2A  += __shfl_xor_sync(0xffffffffu, q2A,  o);
        q1A  += __shfl_xor_sync(0xffffffffu, q1A,  o);
        r1A  += __shfl_xor_sync(0xffffffffu, r1A,  o);
        sxB  += __shfl_xor_sync(0xffffffffu, sxB,  o);
        sxxB += __shfl_xor_sync(0xffffffffu, sxxB, o);
        q2B  += __shfl_xor_sync(0xffffffffu, q2B,  o);
        q1B  += __shfl_xor_sync(0xffffffffu, q1B,  o);
        r1B  += __shfl_xor_sync(0xffffffffu, r1B,  o);
    }
    if (q == 0) {
        float Q0 = gCst[0], R0 = gCst[1], B2 = gCst[2];
        const float invD = 1.f / 512.f;
        {
            float mu = sxA * invD;
            float var = sxxA * invD - mu * mu;
            float istd = rsqrtf(var + 1e-5f);
            float ysq = istd * istd * (q2A - 2.f * mu * q1A + mu * mu * Q0)
                      + 2.f * istd * (r1A - mu * R0) + B2;
            float inv = 1.f / fmaxf(sqrtf(fmaxf(ysq, 0.f)), 1e-12f);
            float4 abc = make_float4(istd * inv, -istd * mu * inv, inv, 0.f);
            sABS[w * 16 + rq] = abc;
            if (r0 < n) gABC[r0] = abc;
        }
        {
            float mu = sxB * invD;
            float var = sxxB * invD - mu * mu;
            float istd = rsqrtf(var + 1e-5f);
            float ysq = istd * istd * (q2B - 2.f * mu * q1B + mu * mu * Q0)
                      + 2.f * istd * (r1B - mu * R0) + B2;
            float inv = 1.f / fmaxf(sqrtf(fmaxf(ysq, 0.f)), 1e-12f);
            float4 abc = make_float4(istd * inv, -istd * mu * inv, inv, 0.f);
            sABS[w * 16 + rq + 8] = abc;
            if (r1 < n) gABC[r1] = abc;
        }
    }

    __syncthreads();   // everyone done reading B -> overlay masks
    {
        int rl = w * 16 + rq;
        int cb = q * 2;
#pragma unroll
        for (int nt = 0; nt < 4; nt++) {
            Msm[rl * 36 + nt * 8 + cb]           = acc[nt][0];
            Msm[rl * 36 + nt * 8 + cb + 1]       = acc[nt][1];
            Msm[(rl + 8) * 36 + nt * 8 + cb]     = acc[nt][2];
            Msm[(rl + 8) * 36 + nt * 8 + cb + 1] = acc[nt][3];
        }
    }
    __syncthreads();

    // epilogue: one thread per token (threads 0..127)
    if (tid < 128) {
        int tok = tokBase + tid;
        if (tok < n) {
            float4 abc = sABS[tid];
            float m[32];
            float mx[4];
#pragma unroll
            for (int k = 0; k < 4; k++) {
                float best = -1e30f;
#pragma unroll
                for (int mm = 0; mm < 8; mm++) {
                    int j = k * 8 + mm;
                    float v = abc.x * Msm[tid * 36 + j] + abc.y * sS1[j] + abc.z * sS2[j];
                    m[j] = v;
                    best = fmaxf(best, v);
                }
                mx[k] = best;
            }
            float mu = 0.25f * (mx[0] + mx[1] + mx[2] + mx[3]);
            float var = 0.f;
#pragma unroll
            for (int k = 0; k < 4; k++) { float d = mx[k] - mu; var += d * d; }
            var *= 0.25f;
            float is4 = 1.f / sqrtf(var + 1e-5f);
            float o[4];
            int pred = 0; float bo = -1e30f;
#pragma unroll
            for (int k = 0; k < 4; k++) {
                o[k] = (mx[k] - mu) * is4 * mg[k] + mb[k];
                if (o[k] > bo) { bo = o[k]; pred = k; }
            }
            *(float4*)(outseg + (size_t)tok * 4) = make_float4(o[0], o[1], o[2], o[3]);
            gPred[tok] = (unsigned char)pred;

            int kk = gt[tok];
            float e[8];
#pragma unroll
            for (int mm = 0; mm < 8; mm++) e[mm] = expf(m[kk * 8 + mm] * INV_EPS);
            *(float4*)(gE + (size_t)tok * 8)     = make_float4(e[0], e[1], e[2], e[3]);
            *(float4*)(gE + (size_t)tok * 8 + 4) = make_float4(e[4], e[5], e[6], e[7]);
#pragma unroll
            for (int mm = 0; mm < 8; mm++)
                atomicAdd(&sCp[tid >> 5][kk * 8 + mm], e[mm]);
            atomicAdd(&sBp[kk], 1.f);
        }
    }
    __syncthreads();
    if (tid < JJ) {
        float s = sCp[0][tid] + sCp[1][tid] + sCp[2][tid] + sCp[3][tid];
        if (s != 0.f) atomicAdd(&gC[0][tid], s);
    }
    if (tid < KCLS && sBp[tid] != 0.f) atomicAdd(&gBcnt[tid], sBp[tid]);
}

// ---------------- kernel 3: one sinkhorn column iteration --------------------
__global__ void __launch_bounds__(256) sinkIterKernel(const int* __restrict__ gt,
                                                      int n, int src, int dst) {
    __shared__ float alpha[JJ];
    __shared__ float Cp[8][JJ];
    __shared__ float Bk[KCLS];
    int tid = threadIdx.x;
    int wrp = tid >> 5;
    if (tid < JJ) alpha[tid] = 1.f / fmaxf(8.f * gC[src][tid], 1e-30f);
    if (tid < 8 * JJ) ((float*)Cp)[tid] = 0.f;
    if (tid < KCLS) Bk[tid] = fmaxf(gBcnt[tid], 1.f);
    __syncthreads();

    int stride = gridDim.x * blockDim.x;
    for (int tok = blockIdx.x * blockDim.x + tid; tok < n; tok += stride) {
        int k = gt[tok];
        float4 a = *(const float4*)(gE + (size_t)tok * 8);
        float4 b4 = *(const float4*)(gE + (size_t)tok * 8 + 4);
        float e[8] = {a.x, a.y, a.z, a.w, b4.x, b4.y, b4.z, b4.w};
        float denom = 0.f;
#pragma unroll
        for (int mm = 0; mm < 8; mm++) denom += e[mm] * alpha[k * 8 + mm];
        float beta = 1.f / fmaxf(Bk[k] * denom, 1e-30f);
#pragma unroll
        for (int mm = 0; mm < 8; mm++) atomicAdd(&Cp[wrp][k * 8 + mm], e[mm] * beta);
    }
    __syncthreads();
    if (tid < JJ) {
        float s = 0.f;
#pragma unroll
        for (int w = 0; w < 8; w++) s += Cp[w][tid];
        if (s != 0.f) atomicAdd(&gC[dst][tid], s);
    }
}

// ---------------- kernel 4: bucket assignment --------------------------------
__global__ void __launch_bounds__(256) bucketKernel(const int* __restrict__ gt, int n) {
    __shared__ float invc[JJ];
    int tid = threadIdx.x;
    if (tid < JJ) invc[tid] = 1.f / fmaxf(gC[2][tid], 1e-30f);
    __syncthreads();
    int stride = gridDim.x * blockDim.x;
    for (int tok = blockIdx.x * blockDim.x + tid; tok < n; tok += stride) {
        int k = gt[tok];
        unsigned char bkt = 255;
        if (gPred[tok] == (unsigned char)k) {
            float4 a = *(const float4*)(gE + (size_t)tok * 8);
            float4 b4 = *(const float4*)(gE + (size_t)tok * 8 + 4);
            float e[8] = {a.x, a.y, a.z, a.w, b4.x, b4.y, b4.z, b4.w};
            float best = -1e30f; int bi = 0;
#pragma unroll
            for (int mm = 0; mm < 8; mm++) {
                float v = e[mm] * invc[k * 8 + mm];
                if (v > best) { best = v; bi = mm; }
            }
            bkt = (unsigned char)(k * 8 + bi);
        }
        gBucket[tok] = bkt;
    }
}

// ---------------- kernel 5: aggregation (register accumulators) --------------
#define AGG_SLICES 88
__global__ void __launch_bounds__(256) aggKernel(const float* __restrict__ X,
                                                 const float* __restrict__ g,
                                                 const float* __restrict__ b,
                                                 int n) {
    int l = threadIdx.x & 31;
    int wgid = blockIdx.x * 8 + (threadIdx.x >> 5);
    int bucket = wgid & 31;
    int slice = wgid >> 5;
    if (slice >= AGG_SLICES) return;

    int chunk = (n + AGG_SLICES - 1) / AGG_SLICES;
    int start = slice * chunk;
    int end = min(start + chunk, n);

    float gl[16], bl[16], acc[16];
#pragma unroll
    for (int i = 0; i < 16; i++) {
        gl[i] = g[l + 32 * i];
        bl[i] = b[l + 32 * i];
        acc[i] = 0.f;
    }
    int cnt = 0;

    for (int t0 = start; t0 < end; t0 += 32) {
        int tok = t0 + l;
        int myb = (tok < end) ? (int)gBucket[tok] : -1;
        unsigned mask = __ballot_sync(0xffffffffu, myb == bucket);
        cnt += __popc(mask);
        while (mask) {
            int bit = __ffs(mask) - 1;
            mask &= mask - 1;
            int th = t0 + bit;
            float4 abc = gABC[th];
            const float* x = X + (size_t)th * DD;
#pragma unroll
            for (int i = 0; i < 16; i++) {
                acc[i] += fmaf(abc.x * gl[i], x[l + 32 * i],
                               fmaf(abc.y, gl[i], abc.z * bl[i]));
            }
        }
    }
#pragma unroll
    for (int i = 0; i < 16; i++)
        if (acc[i] != 0.f) atomicAdd(&gF[bucket * DD + l + 32 * i], acc[i]);
    if (l == 0 && cnt > 0) atomicAdd(&gNcnt[bucket], (float)cnt);
}

// ---------------- kernel 6: finalize new prototypes ---------------------------
__global__ void finalKernel(float* __restrict__ outp) {
    int tid = threadIdx.x;
    int w = tid >> 5, l = tid & 31;
    int k = w >> 3;

    float nj = gNcnt[w];
    float nsum = 0.f;
#pragma unroll
    for (int mm = 0; mm < 8; mm++) nsum += gNcnt[k * 8 + mm];
    bool valid = (nj != 0.f) && (gBcnt[k] > 0.f) && (nsum > 0.f);

    float v[16];
    float ss = 0.f;
#pragma unroll
    for (int i = 0; i < 16; i++) {
        v[i] = gF[w * DD + l + 32 * i];
        ss += v[i] * v[i];
    }
#pragma unroll
    for (int o = 16; o > 0; o >>= 1) ss += __shfl_xor_sync(0xffffffffu, ss, o);
    float inv = 1.f / fmaxf(sqrtf(ss), 1e-12f);

    float out[16];
    float ss2 = 0.f;
#pragma unroll
    for (int i = 0; i < 16; i++) {
        float fn = v[i] * inv;
        float base = gPN[w * DD + l + 32 * i];
        float r = valid ? (GAMMA_M * base + (1.f - GAMMA_M) * fn) : base;
        out[i] = r;
        ss2 += r * r;
    }
#pragma unroll
    for (int o = 16; o > 0; o >>= 1) ss2 += __shfl_xor_sync(0xffffffffu, ss2, o);
    float inv2 = 1.f / fmaxf(sqrtf(ss2), 1e-12f);
#pragma unroll
    for (int i = 0; i < 16; i++)
        outp[w * DD + l + 32 * i] = out[i] * inv2;
}

// ---------------- launch ------------------------------------------------------
extern "C" void kernel_launch(void* const* d_in, const int* in_sizes, int n_in,
                              void* d_out, int out_size) {
    const float* feats  = (const float*)d_in[0];
    const float* ln_g   = (const float*)d_in[1];
    const float* ln_b   = (const float*)d_in[2];
    const float* mg     = (const float*)d_in[3];
    const float* mb     = (const float*)d_in[4];
    const float* protos = (const float*)d_in[5];
    const int*   gt     = (const int*)d_in[6];

    int n = in_sizes[0] / DD;
    float* outseg = (float*)d_out;
    float* outp   = (float*)d_out + (size_t)(out_size - JJ * DD);

    cudaFuncSetAttribute(fusedKernel, cudaFuncAttributeMaxDynamicSharedMemorySize, DSM_BYTES);

    initKernel<<<1, 1024>>>(protos, ln_g, ln_b);
    nopKernel<<<1, 32>>>(0);
    nopKernel<<<1, 32>>>(1);
    fusedKernel<<<(n + 127) / 128, 256, DSM_BYTES>>>(feats, gt, mg, mb, outseg, n);
    sinkIterKernel<<<512, 256>>>(gt, n, 0, 1);
    sinkIterKernel<<<512, 256>>>(gt, n, 1, 2);
    bucketKernel<<<512, 256>>>(gt, n);
    aggKernel<<<(32 * AGG_SLICES + 7) / 8, 256>>>(feats, ln_g, ln_b, n);
    finalKernel<<<1, 1024>>>(outp);
}